// round 2
// baseline (speedup 1.0000x reference)
#include <cuda_runtime.h>

// QuantumConvLayer: probs = [c^4, c^2 s^2, s^4, s^2 c^2] with
// c^2 = cos^2(x/2), s^2 = sin^2(x/2), x = inputs[i,0].
// Pure HBM-bound elementwise map: 16B read-sector-coverage + 16B write per row.

__global__ void __launch_bounds__(256) qconv_kernel(
    const float* __restrict__ in,   // [N,4] row-major
    float4* __restrict__ out,       // [N] float4
    int n)
{
    int i = blockIdx.x * blockDim.x + threadIdx.x;
    if (i >= n) return;

    float half = 0.5f * __ldg(in + 4 * (size_t)i);
    float s, c;
    sincosf(half, &s, &c);
    float c2 = c * c;
    float s2 = s * s;

    float4 p;
    p.x = c2 * c2;
    p.y = c2 * s2;
    p.z = s2 * s2;
    p.w = s2 * c2;
    out[i] = p;
}

extern "C" void kernel_launch(void* const* d_in, const int* in_sizes, int n_in,
                              void* d_out, int out_size)
{
    const float* in = (const float*)d_in[0];
    float4* out = (float4*)d_out;
    int n = in_sizes[0] / 4;   // rows

    int block = 256;
    int grid = (n + block - 1) / block;
    qconv_kernel<<<grid, block>>>(in, out, n);
}

// round 3
// speedup vs baseline: 1.0148x; 1.0148x over previous
#include <cuda_runtime.h>

// QuantumConvLayer: probs = [c^4, c^2 s^2, s^4, s^2 c^2],
// c^2 = cos^2(x/2) = (1+cos x)/2, s^2 = (1-cos x)/2, x = inputs[i,0].
// HBM-bound: 256MB read (every 32B sector of input touched) + 256MB write.
// R2: 4x thread coarsening (front-batched loads, MLP_p1=4) + single __cosf
// of the full angle instead of sincosf(half).

#define ROWS_PER_THREAD 4

__global__ void __launch_bounds__(256) qconv_kernel(
    const float* __restrict__ in,   // [N,4] row-major; only col 0 read
    float4* __restrict__ out,       // [N]
    int n)
{
    // Block tile of 256*4 = 1024 rows; thread t handles rows tile+t+256*k
    int tile = blockIdx.x * (256 * ROWS_PER_THREAD);
    int t = threadIdx.x;

    float x[ROWS_PER_THREAD];
    int row[ROWS_PER_THREAD];

    // Front-batch all loads (independent -> 4 outstanding LDGs per thread)
#pragma unroll
    for (int k = 0; k < ROWS_PER_THREAD; k++) {
        row[k] = tile + t + 256 * k;
        if (row[k] < n)
            x[k] = __ldg(in + 4 * (size_t)row[k]);
        else
            x[k] = 0.0f;
    }

#pragma unroll
    for (int k = 0; k < ROWS_PER_THREAD; k++) {
        float cx = __cosf(x[k]);
        float c2 = 0.5f + 0.5f * cx;   // cos^2(x/2)
        float s2 = 0.5f - 0.5f * cx;   // sin^2(x/2)
        float cs = c2 * s2;
        float4 p;
        p.x = c2 * c2;
        p.y = cs;
        p.z = s2 * s2;
        p.w = cs;
        if (row[k] < n)
            out[row[k]] = p;
    }
}

extern "C" void kernel_launch(void* const* d_in, const int* in_sizes, int n_in,
                              void* d_out, int out_size)
{
    const float* in = (const float*)d_in[0];
    float4* out = (float4*)d_out;
    int n = in_sizes[0] / 4;   // rows

    int rows_per_block = 256 * ROWS_PER_THREAD;
    int grid = (n + rows_per_block - 1) / rows_per_block;
    qconv_kernel<<<grid, 256>>>(in, out, n);
}